// round 3
// baseline (speedup 1.0000x reference)
#include <cuda_runtime.h>
#include <cuda_bf16.h>

#define NN 100000
#define EE 1600000
#define GG 512

__device__ float g_h[NN * 100];     // node features / conv output (h)
__device__ float g_xd[NN * 100];    // layer-1 dst-transformed features
__device__ float g_agg[NN * 100];   // aggregation output (agg + xd)
__device__ float g_hid[NN * 200];   // MLP hidden
__device__ int   g_cnt[NN];         // in-degree per node
__device__ int   g_off[NN];         // CSR offsets (exclusive scan of cnt)
__device__ int   g_cur[NN];         // scatter cursors
__device__ int   g_csr[EE];         // src ids grouped by dst
__device__ float g_rsum[GG * 100];
__device__ float g_rmax[GG * 100];
__device__ float g_enc[GG * 200];
__device__ float g_z[GG * 100];
__device__ int   g_cntg[GG];

__device__ __forceinline__ int clampi(int v, int hi) {
    return v < 0 ? 0 : (v >= hi ? hi - 1 : v);
}

// ---------------- init / histograms ----------------

__global__ void k_init() {
    int i = blockIdx.x * blockDim.x + threadIdx.x;
    if (i < NN) g_cnt[i] = 0;
    if (i < GG) g_cntg[i] = 0;
    if (i < GG * 200) g_enc[i] = 0.0f;
}

__global__ void k_zero_read() {
    int i = blockIdx.x * blockDim.x + threadIdx.x;
    if (i < GG * 100) { g_rsum[i] = 0.0f; g_rmax[i] = 0.0f; }
}

__global__ void k_hist(const int* __restrict__ ei) {
    int e = blockIdx.x * blockDim.x + threadIdx.x;
    if (e < EE) atomicAdd(&g_cnt[clampi(ei[EE + e], NN)], 1);
}

__global__ void k_bhist(const int* __restrict__ batch) {
    int n = blockIdx.x * blockDim.x + threadIdx.x;
    if (n < NN) atomicAdd(&g_cntg[clampi(batch[n], GG)], 1);
}

// single-block exclusive scan of g_cnt -> g_off, g_cur
__global__ void k_scan() {
    __shared__ int s[1024];
    __shared__ int carry;
    int tid = threadIdx.x;
    if (tid == 0) carry = 0;
    __syncthreads();
    for (int base = 0; base < NN; base += 1024) {
        int idx = base + tid;
        int v = (idx < NN) ? g_cnt[idx] : 0;
        s[tid] = v;
        __syncthreads();
        for (int d = 1; d < 1024; d <<= 1) {
            int t = (tid >= d) ? s[tid - d] : 0;
            __syncthreads();
            s[tid] += t;
            __syncthreads();
        }
        int excl = carry + s[tid] - v;
        if (idx < NN) { g_off[idx] = excl; g_cur[idx] = excl; }
        __syncthreads();
        if (tid == 0) carry += s[1023];
        __syncthreads();
    }
}

__global__ void k_scatter(const int* __restrict__ ei) {
    int e = blockIdx.x * blockDim.x + threadIdx.x;
    if (e < EE) {
        int d = clampi(ei[EE + e], NN);
        int p = atomicAdd(&g_cur[d], 1);
        if (p >= 0 && p < EE) g_csr[p] = clampi(ei[e], NN);
    }
}

// ---------------- layer-1 input linears (K=10) ----------------

__global__ void k_lin10(const float* __restrict__ x,
                        const float* __restrict__ ws, const float* __restrict__ bs,
                        const float* __restrict__ wd, const float* __restrict__ bd) {
    __shared__ float sws[1000], sbs[100], swd[1000], sbd[100];
    int tid = threadIdx.x;
    for (int i = tid; i < 1000; i += blockDim.x) { sws[i] = ws[i]; swd[i] = wd[i]; }
    for (int i = tid; i < 100; i += blockDim.x)  { sbs[i] = bs[i]; sbd[i] = bd[i]; }
    __syncthreads();
    int n = blockIdx.x * blockDim.x + tid;
    if (n >= NN) return;
    float xr[10];
#pragma unroll
    for (int k = 0; k < 10; k++) xr[k] = x[n * 10 + k];
    for (int o = 0; o < 100; o++) {
        float a = sbs[o], b = sbd[o];
#pragma unroll
        for (int k = 0; k < 10; k++) {
            a += xr[k] * sws[o * 10 + k];
            b += xr[k] * swd[o * 10 + k];
        }
        g_h[n * 100 + o] = a;
        g_xd[n * 100 + o] = b;
    }
}

// ---------------- softmax aggregation (warp per dst node) ----------------

__global__ void k_agg(int use_gxd) {
    int w = (blockIdx.x * blockDim.x + threadIdx.x) >> 5;
    if (w >= NN) return;
    int lane = threadIdx.x & 31;
    int start = g_off[w];
    int deg = g_cnt[w];
    const float* xd = use_gxd ? g_xd : g_h;
    bool p3 = lane < 4;
    const float EPS_MSG = 1e-7f;
    const float EPS_SM = 1e-16f;

    float m0 = -1e30f, m1 = -1e30f, m2 = -1e30f, m3 = -1e30f;
    for (int i = 0; i < deg; i++) {
        int s = g_csr[start + i];
        const float* hr = g_h + (long)s * 100;
        float v0 = fmaxf(hr[lane], 0.0f) + EPS_MSG;       m0 = fmaxf(m0, v0);
        float v1 = fmaxf(hr[lane + 32], 0.0f) + EPS_MSG;  m1 = fmaxf(m1, v1);
        float v2 = fmaxf(hr[lane + 64], 0.0f) + EPS_MSG;  m2 = fmaxf(m2, v2);
        if (p3) { float v3 = fmaxf(hr[lane + 96], 0.0f) + EPS_MSG; m3 = fmaxf(m3, v3); }
    }
    float d0 = 0, d1 = 0, d2 = 0, d3 = 0;
    float n0 = 0, n1 = 0, n2 = 0, n3 = 0;
    for (int i = 0; i < deg; i++) {
        int s = g_csr[start + i];
        const float* hr = g_h + (long)s * 100;
        float v0 = fmaxf(hr[lane], 0.0f) + EPS_MSG;
        float v1 = fmaxf(hr[lane + 32], 0.0f) + EPS_MSG;
        float v2 = fmaxf(hr[lane + 64], 0.0f) + EPS_MSG;
        float e0 = __expf(v0 - m0); d0 += e0; n0 += e0 * v0;
        float e1 = __expf(v1 - m1); d1 += e1; n1 += e1 * v1;
        float e2 = __expf(v2 - m2); d2 += e2; n2 += e2 * v2;
        if (p3) {
            float v3 = fmaxf(hr[lane + 96], 0.0f) + EPS_MSG;
            float e3 = __expf(v3 - m3); d3 += e3; n3 += e3 * v3;
        }
    }
    long base = (long)w * 100;
    g_agg[base + lane]      = n0 / (d0 + EPS_SM) + xd[base + lane];
    g_agg[base + lane + 32] = n1 / (d1 + EPS_SM) + xd[base + lane + 32];
    g_agg[base + lane + 64] = n2 / (d2 + EPS_SM) + xd[base + lane + 64];
    if (p3) g_agg[base + lane + 96] = n3 / (d3 + EPS_SM) + xd[base + lane + 96];
}

// ---------------- tiled SGEMM for MLP layers ----------------
// EPI==0: A=g_agg (FIN=100) -> C=g_hid (FOUT=200), epilogue bias+BN+relu
// EPI==1: A=g_hid (FIN=200) -> C=g_h   (FOUT=100), epilogue bias+relu (conv output relu)

template <int FIN, int EPI>
__global__ void __launch_bounds__(256)
k_gemm(const float* __restrict__ W, const float* __restrict__ bias,
       const float* __restrict__ bng, const float* __restrict__ bnb) {
    constexpr int FOUT = (EPI == 0) ? 200 : 100;
    const float* A = (EPI == 0) ? g_agg : g_hid;
    float* C = (EPI == 0) ? g_hid : g_h;

    const int KC = 20;
    __shared__ float As[128][KC + 1];
    __shared__ float Bs[KC][112];

    int tid = threadIdx.x;
    int tx = tid & 15;        // 16 col threads
    int ty = tid >> 4;        // 16 row threads
    int row0 = blockIdx.x * 128;
    int col0 = blockIdx.y * 100;

    float acc[8][7];
#pragma unroll
    for (int i = 0; i < 8; i++)
#pragma unroll
        for (int j = 0; j < 7; j++) acc[i][j] = 0.0f;

    for (int k0 = 0; k0 < FIN; k0 += KC) {
        for (int idx = tid; idx < 128 * KC; idx += 256) {
            int r = idx / KC, kk = idx % KC;
            int grow = row0 + r;
            As[r][kk] = (grow < NN) ? A[(long)grow * FIN + k0 + kk] : 0.0f;
        }
        for (int idx = tid; idx < KC * 112; idx += 256) {
            int kk = idx / 112, m = idx % 112;
            Bs[kk][m] = (m < 100) ? W[(long)(col0 + m) * FIN + k0 + kk] : 0.0f;
        }
        __syncthreads();
#pragma unroll
        for (int kk = 0; kk < KC; kk++) {
            float a[8], b[7];
#pragma unroll
            for (int i = 0; i < 8; i++) a[i] = As[ty + 16 * i][kk];
#pragma unroll
            for (int j = 0; j < 7; j++) b[j] = Bs[kk][tx + 16 * j];
#pragma unroll
            for (int i = 0; i < 8; i++)
#pragma unroll
                for (int j = 0; j < 7; j++) acc[i][j] += a[i] * b[j];
        }
        __syncthreads();
    }

    const float bnscale = rsqrtf(1.0f + 1e-5f);
#pragma unroll
    for (int i = 0; i < 8; i++) {
        int r = row0 + ty + 16 * i;
        if (r >= NN) continue;
#pragma unroll
        for (int j = 0; j < 7; j++) {
            int c = tx + 16 * j;
            if (c >= 100) continue;
            int ch = col0 + c;
            float v = acc[i][j] + bias[ch];
            if (EPI == 0) {
                v = v * (bng[ch] * bnscale) + bnb[ch];
                v = fmaxf(v, 0.0f);
            } else {
                v = fmaxf(v, 0.0f);
            }
            C[(long)r * FOUT + ch] = v;
        }
    }
}

// ---------------- readout ----------------

__global__ void k_readout(const int* __restrict__ batch) {
    int i = blockIdx.x * blockDim.x + threadIdx.x;
    if (i >= NN * 100) return;
    int n = i / 100, f = i - n * 100;
    float v = g_h[i];               // v >= 0 (post-relu)
    int g = clampi(batch[n], GG);
    atomicAdd(&g_rsum[g * 100 + f], v);
    atomicMax((int*)&g_rmax[g * 100 + f], __float_as_int(v));
}

__global__ void k_combine() {
    int i = blockIdx.x * blockDim.x + threadIdx.x;
    if (i >= GG * 100) return;
    int g = i / 100, f = i - g * 100;
    float c = (float)g_cntg[g];
    float mean = g_rsum[i] / fmaxf(c, 1.0f);
    g_enc[g * 200 + f] += mean;          // relu is identity (>=0)
    g_enc[g * 200 + 100 + f] += g_rmax[i];
}

// ---------------- head ----------------

__global__ void k_fc1(const float* __restrict__ w, const float* __restrict__ b) {
    int i = blockIdx.x * blockDim.x + threadIdx.x;
    if (i >= GG * 100) return;
    int g = i / 100, o = i - g * 100;
    const float* er = g_enc + g * 200;
    const float* wr = w + o * 200;
    float a = b[o];
#pragma unroll 4
    for (int k = 0; k < 200; k++) a += er[k] * wr[k];
    g_z[i] = fmaxf(a, 0.0f);
}

__global__ void k_outenc(float* __restrict__ out) {
    int i = blockIdx.x * blockDim.x + threadIdx.x;
    if (i < GG * 200) out[1024 + i] = g_enc[i];
}

__global__ void k_cls(const float* __restrict__ w, const float* __restrict__ b,
                      float* __restrict__ out) {
    int i = blockIdx.x * blockDim.x + threadIdx.x;
    if (i >= GG * 2) return;
    int g = i >> 1, o = i & 1;
    const float* zr = g_z + g * 100;
    const float* wr = w + o * 100;
    float a = b[o];
#pragma unroll 4
    for (int k = 0; k < 100; k++) a += zr[k] * wr[k];
    out[g * 2 + o] = a;
}

// ---------------- launch ----------------

extern "C" void kernel_launch(void* const* d_in, const int* in_sizes, int n_in,
                              void* d_out, int out_size) {
    const float* x = (const float*)d_in[0];
    const int* ei = (const int*)d_in[1];      // int32! (JAX default x64-disabled)
    const int* batch = (const int*)d_in[2];   // int32!
    const float* c1_src_w = (const float*)d_in[3];
    const float* c1_src_b = (const float*)d_in[4];
    const float* c1_dst_w = (const float*)d_in[5];
    const float* c1_dst_b = (const float*)d_in[6];
    // per-conv MLP params: w1,b1,g,be,w2,b2
    const float* cw1[3] = {(const float*)d_in[7],  (const float*)d_in[13], (const float*)d_in[19]};
    const float* cb1[3] = {(const float*)d_in[8],  (const float*)d_in[14], (const float*)d_in[20]};
    const float* cg[3]  = {(const float*)d_in[9],  (const float*)d_in[15], (const float*)d_in[21]};
    const float* cbe[3] = {(const float*)d_in[10], (const float*)d_in[16], (const float*)d_in[22]};
    const float* cw2[3] = {(const float*)d_in[11], (const float*)d_in[17], (const float*)d_in[23]};
    const float* cb2[3] = {(const float*)d_in[12], (const float*)d_in[18], (const float*)d_in[24]};
    const float* fc1_w = (const float*)d_in[25];
    const float* fc1_b = (const float*)d_in[26];
    const float* cls_w = (const float*)d_in[27];
    const float* cls_b = (const float*)d_in[28];
    float* out = (float*)d_out;

    const int T = 256;

    // CSR build + graph counts
    k_init<<<(GG * 200 + T - 1) / T, T>>>();
    k_hist<<<(EE + T - 1) / T, T>>>(ei);
    k_bhist<<<(NN + T - 1) / T, T>>>(batch);
    k_scan<<<1, 1024>>>();
    k_scatter<<<(EE + T - 1) / T, T>>>(ei);

    // layer-1 src/dst linears
    k_lin10<<<(NN + T - 1) / T, T>>>(x, c1_src_w, c1_src_b, c1_dst_w, c1_dst_b);

    dim3 g1((NN + 127) / 128, 2);  // FOUT=200
    dim3 g2((NN + 127) / 128, 1);  // FOUT=100

    for (int l = 0; l < 3; l++) {
        k_agg<<<(NN * 32 + T - 1) / T, T>>>(l == 0 ? 1 : 0);
        k_gemm<100, 0><<<g1, 256>>>(cw1[l], cb1[l], cg[l], cbe[l]);
        k_gemm<200, 1><<<g2, 256>>>(cw2[l], cb2[l], nullptr, nullptr);
        k_zero_read<<<(GG * 100 + T - 1) / T, T>>>();
        k_readout<<<(NN * 100 + T - 1) / T, T>>>(batch);
        k_combine<<<(GG * 100 + T - 1) / T, T>>>();
    }

    k_fc1<<<(GG * 100 + T - 1) / T, T>>>(fc1_w, fc1_b);
    k_outenc<<<(GG * 200 + T - 1) / T, T>>>(out);
    k_cls<<<(GG * 2 + T - 1) / T, T>>>(cls_w, cls_b, out);
}